// round 1
// baseline (speedup 1.0000x reference)
#include <cuda_runtime.h>

// Radon forward projection, sm_103a.
// out[b, a, det] = (DT/12) * sum_k bilinear(x[b], i0(k), i1(k))
// i0(k) = c0 + k*d0, i1(k) = c1 + k*d1  (linear in sample index k)
//
// Image cached in shared memory with a zero border so the bilinear taps for
// floor indices in [-1, 128] are branch-free. Per-ray exact k-interval
// clipping removes the ~50% of samples that fall entirely outside the image.

#define STRIDE 133               // row stride in floats (odd: conflict-free vertical rays)
#define PAD_ROWS 131             // covers original rows -1..129 (+1 shift)
#define SMEM_FLOATS (PAD_ROWS * STRIDE)
#define SMEM_BYTES (SMEM_FLOATS * 4)

#define N_IMGc 128
#define N_ANGc 285
#define N_DETc 183
#define N_Tc   384
#define GRID_X 55                // angle stride; 55*8 = 440 blocks = 1 wave @ occ 3

__global__ __launch_bounds__(192, 3)
void radon_fp_kernel(const float* __restrict__ x, float* __restrict__ out)
{
    extern __shared__ float img[];
    const int tid = threadIdx.x;
    const int b = blockIdx.y;

    // Zero padded image (border must be 0)
    for (int i = tid; i < SMEM_FLOATS; i += 192) img[i] = 0.0f;
    __syncthreads();

    // Fill interior: original pixel (r,c) -> img[(r+1)*STRIDE + (c+1)]
    const float* gx = x + b * (N_IMGc * N_IMGc);
    for (int i = tid; i < N_IMGc * N_IMGc; i += 192) {
        int r = i >> 7, c = i & 127;
        img[(r + 1) * STRIDE + (c + 1)] = gx[i];
    }
    __syncthreads();

    const double RHOd = 28.284271247461902;   // 20*sqrt(2)
    const double DTd  = 2.0 * RHOd / 384.0;
    const double DXd  = 0.3125;               // 40/128
    const double PId  = 3.141592653589793;

    const int det = tid;
    const double s  = -RHOd + (det + 0.5) * (2.0 * RHOd / 183.0);
    const double t0 = -RHOd + 0.5 * DTd;
    const float scale = (float)(DTd / 12.0);

    for (int a = blockIdx.x; a < N_ANGc; a += GRID_X) {
        if (det < N_DETc) {
            double ang = (a + 0.5) * (PId / (double)N_ANGc);
            double sn = sin(ang), cs = cos(ang);

            // i0 = ((-s*sn + t*cs) + 20)/DX - 0.5,  t = t0 + k*DT
            double d0 = DTd * cs / DXd;
            double d1 = DTd * sn / DXd;
            double c0 = ((-s * sn + t0 * cs) + 20.0) / DXd - 0.5;
            double c1 = (( s * cs + t0 * sn) + 20.0) / DXd - 0.5;

            // Valid (nonzero, memory-safe) window: i in [-0.999, 128.5].
            // Lower -0.999 guarantees floor >= -1 after float rounding (<=3e-5 err);
            // contributions lost in (-1,-0.999) weigh <= 1e-3 on a single sample.
            const double LO = -0.999, HI = 128.5;
            double klo = 0.0, khi = 383.0;

            if (d0 > 1e-9)       { klo = fmax(klo, (LO - c0) / d0); khi = fmin(khi, (HI - c0) / d0); }
            else if (d0 < -1e-9) { klo = fmax(klo, (HI - c0) / d0); khi = fmin(khi, (LO - c0) / d0); }
            else if (c0 < LO || c0 > HI) khi = -1.0;

            if (d1 > 1e-9)       { klo = fmax(klo, (LO - c1) / d1); khi = fmin(khi, (HI - c1) / d1); }
            else if (d1 < -1e-9) { klo = fmax(klo, (HI - c1) / d1); khi = fmin(khi, (LO - c1) / d1); }
            else if (c1 < LO || c1 > HI) khi = -1.0;

            klo = fmin(fmax(klo, 0.0), 500.0);
            khi = fmin(fmax(khi, -1.0), 383.0);
            int k0 = (int)ceil(klo);
            int k1 = (int)floor(khi);

            float c0f = (float)c0, d0f = (float)d0;
            float c1f = (float)c1, d1f = (float)d1;
            float acc = 0.0f;

            #pragma unroll 4
            for (int k = k0; k <= k1; ++k) {
                float kf = (float)k;
                float i0 = fmaf(kf, d0f, c0f);
                float i1 = fmaf(kf, d1f, c1f);
                int x0 = __float2int_rd(i0);
                int x1 = __float2int_rd(i1);
                float f0 = i0 - (float)x0;
                float f1 = i1 - (float)x1;
                const float* p = img + (x0 * STRIDE + x1 + (STRIDE + 1));
                float v00 = p[0];
                float v01 = p[1];
                float v10 = p[STRIDE];
                float v11 = p[STRIDE + 1];
                float top = fmaf(f1, v01 - v00, v00);
                float bot = fmaf(f1, v11 - v10, v10);
                acc += fmaf(f0, bot - top, top);
            }

            out[(b * N_ANGc + a) * N_DETc + det] = acc * scale;
        }
    }
}

extern "C" void kernel_launch(void* const* d_in, const int* in_sizes, int n_in,
                              void* d_out, int out_size)
{
    const float* x = (const float*)d_in[0];
    float* out = (float*)d_out;

    cudaFuncSetAttribute(radon_fp_kernel,
                         cudaFuncAttributeMaxDynamicSharedMemorySize, SMEM_BYTES);

    dim3 grid(GRID_X, 8);
    radon_fp_kernel<<<grid, 192, SMEM_BYTES>>>(x, out);
}